// round 13
// baseline (speedup 1.0000x reference)
#include <cuda_runtime.h>
#include <cuda_fp16.h>
#include <cstdint>

#define BATCH 16384
#define H 256
#define H2 288
#define OUTD 10
#define IND 784
#define TSTEPS 50
#define MROWS 128
#define NTHR 512
#define ABLK 65536   // bytes per CTA fp16 image block (128 x 256 x 2)

typedef unsigned long long ull;

// -------- device scratch --------
__device__ float g_X[BATCH * H];
__device__ float g_s0[2][BATCH * OUTD];
__device__ float g_s1[2][BATCH * H];
__device__ float g_s2[2][BATCH * H];
// fp16 swizzled state images (per-CTA 64KB blocks); CTA b owns bytes [b*65536, (b+1)*65536)
__device__ __half g_h1img[BATCH * H], g_h2img[BATCH * H];
// fp16 weight images in [k][n] layout, XOR-swizzled 16B chunks.
// B1[k][n] = W2[k][n]  (P2 = rho(s1) @ W2)
// B2e: rows 0..255 = W2[n][k]; rows 256+o = W0[o][n]; row 266 = b2[n]; rows 267..287 = 0
__device__ __half g_B1[H * H], g_B2e[H2 * H];

__device__ __forceinline__ float rho_f(float x) { return fminf(fmaxf(x, 0.0f), 1.0f); }

__device__ __forceinline__ ull pack2(float a, float b) {
    ull r; asm("mov.b64 %0, {%1, %2};" : "=l"(r) : "f"(a), "f"(b)); return r;
}
__device__ __forceinline__ void fma2(ull &d, ull a, ull b) {
    asm("fma.rn.f32x2 %0, %1, %2, %0;" : "+l"(d) : "l"(a), "l"(b));
}
__device__ __forceinline__ float2 unpack2(ull v) {
    float2 f; asm("mov.b64 {%0, %1}, %2;" : "=f"(f.x), "=f"(f.y) : "l"(v)); return f;
}
__device__ __forceinline__ void cpasync16(char* dst, const char* src) {
    unsigned d = (unsigned)__cvta_generic_to_shared(dst);
    asm volatile("cp.async.cg.shared.global [%0], [%1], 16;" :: "r"(d), "l"(src));
}
__device__ __forceinline__ void cpasync_commit() { asm volatile("cp.async.commit_group;"); }
__device__ __forceinline__ void cpasync_wait0()  { asm volatile("cp.async.wait_group 0;"); }

__device__ __forceinline__ uint32_t smem_u32(const void* p) {
    uint32_t a;
    asm("{ .reg .u64 t; cvta.to.shared.u64 t, %1; cvt.u32.u64 %0, t; }" : "=r"(a) : "l"(p));
    return a;
}
__device__ __forceinline__ void ldsm_x4(uint32_t* r, uint32_t addr) {
    asm volatile("ldmatrix.sync.aligned.m8n8.x4.shared.b16 {%0,%1,%2,%3}, [%4];"
                 : "=r"(r[0]), "=r"(r[1]), "=r"(r[2]), "=r"(r[3]) : "r"(addr));
}
__device__ __forceinline__ void ldsm_x4_t(uint32_t* r, uint32_t addr) {
    asm volatile("ldmatrix.sync.aligned.m8n8.x4.trans.shared.b16 {%0,%1,%2,%3}, [%4];"
                 : "=r"(r[0]), "=r"(r[1]), "=r"(r[2]), "=r"(r[3]) : "r"(addr));
}
__device__ __forceinline__ void mma16816(float* c, const uint32_t* a, uint32_t b0, uint32_t b1) {
    asm volatile("mma.sync.aligned.m16n8k16.row.col.f32.f16.f16.f32 "
        "{%0,%1,%2,%3}, {%4,%5,%6,%7}, {%8,%9}, {%0,%1,%2,%3};"
        : "+f"(c[0]), "+f"(c[1]), "+f"(c[2]), "+f"(c[3])
        : "r"(a[0]), "r"(a[1]), "r"(a[2]), "r"(a[3]), "r"(b0), "r"(b1));
}
__device__ __forceinline__ uint32_t pack_h2(float a, float b) {
    __half ha = __float2half(a), hb = __float2half(b);
    return ((uint32_t)__half_as_ushort(hb) << 16) | __half_as_ushort(ha);
}
// byte offset of element (m, k) inside a 128x256 swizzled fp16 image block
__device__ __forceinline__ uint32_t img_off(int m, int k) {
    return (uint32_t)m * 512u + ((((uint32_t)k >> 3) ^ ((uint32_t)m & 7u)) << 4)
         + ((uint32_t)k & 7u) * 2u;
}

// ---------------- init: fp32 state + initial fp16 images ----------------
__global__ void __launch_bounds__(256) init_kernel(
    const float* __restrict__ s0, const float* __restrict__ s1,
    const float* __restrict__ s2)
{
    int idx = blockIdx.x * 256 + threadIdx.x;
    ((float4*)g_s1[0])[idx] = ((const float4*)s1)[idx];
    ((float4*)g_s2[0])[idx] = ((const float4*)s2)[idx];
    if (idx < BATCH * OUTD / 4)
        ((float4*)g_s0[0])[idx] = ((const float4*)s0)[idx];
    // build initial images (4 consecutive k per thread, same row)
    int e = idx * 4;
    int row = e >> 8, k = e & 255;
    int b = row >> 7, m = row & 127;
    const float* sp1 = s1 + e;
    const float* sp2 = s2 + e;
    uint32_t off = (size_t)0;
    char* base1 = (char*)g_h1img + (size_t)b * ABLK;
    char* base2 = (char*)g_h2img + (size_t)b * ABLK;
    off = img_off(m, k);   // k%8 in {0,4}: both pairs within same 16B chunk
    *(uint32_t*)(base1 + off)     = pack_h2(rho_f(sp1[0]), rho_f(sp1[1]));
    *(uint32_t*)(base1 + off + 4) = pack_h2(rho_f(sp1[2]), rho_f(sp1[3]));
    *(uint32_t*)(base2 + off)     = pack_h2(rho_f(sp2[0]), rho_f(sp2[1]));
    *(uint32_t*)(base2 + off + 4) = pack_h2(rho_f(sp2[2]), rho_f(sp2[3]));
}

// ---------------- build fp16 weight images ----------------
__global__ void __launch_bounds__(H2) img_kernel(
    const float* __restrict__ W2, const float* __restrict__ W0,
    const float* __restrict__ b2)
{
    int n = blockIdx.x, k = threadIdx.x;
    uint32_t off = (uint32_t)k * 512u + ((((uint32_t)n >> 3) ^ ((uint32_t)k & 7u)) << 4)
                 + ((uint32_t)n & 7u) * 2u;
    if (k < H)
        *(__half*)((char*)g_B1 + off) = __float2half(W2[k * H + n]);
    float w;
    if (k < H)              w = W2[n * H + k];
    else if (k < H + OUTD)  w = W0[(k - H) * H + n];
    else if (k == H + OUTD) w = b2[n];
    else                    w = 0.f;
    *(__half*)((char*)g_B2e + off) = __float2half(w);
}

// ---------------- prefix: X = rho(data) @ W4.T + b4 (fp32, once) ----------------
__global__ void __launch_bounds__(256) x_kernel(
    const float* __restrict__ data, const float* __restrict__ W4,
    const float* __restrict__ b4)
{
    __shared__ float As[16 * 66];
    __shared__ float Bs[16 * 66];
    const int tid = threadIdx.x;
    const int i0 = blockIdx.x * 64, j0 = blockIdx.y * 64;
    const int tx = tid & 15, ty = tid >> 4;
    const int kk = tid & 15, rr = tid >> 4;

    ull acc[4][2] = {};
    for (int k0 = 0; k0 < IND; k0 += 16) {
#pragma unroll
        for (int q = 0; q < 4; q++) {
            int r = rr + q * 16;
            As[kk * 66 + r] = rho_f(data[(size_t)(i0 + r) * IND + k0 + kk]);
            Bs[kk * 66 + r] = W4[(size_t)(j0 + r) * IND + k0 + kk];
        }
        __syncthreads();
#pragma unroll
        for (int k = 0; k < 16; k++) {
            ull a[4];
#pragma unroll
            for (int i = 0; i < 4; i++) {
                float av = As[k * 66 + ty * 4 + i];
                a[i] = pack2(av, av);
            }
            ull w0 = *(const ull*)(Bs + k * 66 + tx * 2);
            ull w1 = *(const ull*)(Bs + k * 66 + 32 + tx * 2);
#pragma unroll
            for (int i = 0; i < 4; i++) { fma2(acc[i][0], a[i], w0); fma2(acc[i][1], a[i], w1); }
        }
        __syncthreads();
    }
#pragma unroll
    for (int i = 0; i < 4; i++) {
        size_t row = (size_t)i0 + ty * 4 + i;
        float2 p0 = unpack2(acc[i][0]), p1 = unpack2(acc[i][1]);
        int j0a = j0 + tx * 2, j0b = j0 + 32 + tx * 2;
        *(float2*)(g_X + row * H + j0a) = make_float2(p0.x + b4[j0a], p0.y + b4[j0a + 1]);
        *(float2*)(g_X + row * H + j0b) = make_float2(p1.x + b4[j0b], p1.y + b4[j0b + 1]);
    }
}

// ---------------- SMEM layout (bytes) ----------------
#define SM_A1   0                      // [128][256] fp16 swizzled = 64KB  (rho(s1))
#define SM_A2   65536                  // 64KB (rho(s2))
#define SM_B    131072                 // 2 bufs x 16KB = 32KB
#define SM_W0   163840                 // [10][256] f32
#define SM_RS0  174080                 // [128][10] f32
#define SM_B0V  179200
#define SM_TOTAL (SM_B0V + 64)

// prefetch one 32-k-row weight chunk (16KB) into buffer buf
__device__ __forceinline__ void prefetch_chunk(char* sm, int buf, int tid,
                                               const char* img, int chunk)
{
    char* d = sm + SM_B + buf * 16384 + tid * 32;
    const char* s = img + (size_t)chunk * 16384 + tid * 32;
    cpasync16(d, s); cpasync16(d + 16, s + 16);
    cpasync_commit();
}

__global__ void __launch_bounds__(NTHR, 1) step_kernel(
    int inbuf, int last, float* __restrict__ dout,
    const float* __restrict__ W0, const float* __restrict__ b0)
{
    extern __shared__ char sm[];
    const uint32_t smb = smem_u32(sm);
    const int tid = threadIdx.x;
    const int lane = tid & 31, wid = tid >> 5;
    const size_t row0 = (size_t)blockIdx.x * MROWS;

    const float* __restrict__ s0in = g_s0[inbuf];
    const float* __restrict__ s1in = g_s1[inbuf];
    const float* __restrict__ s2in = g_s2[inbuf];
    float* s0out = last ? dout : g_s0[inbuf ^ 1];
    float* s1out = last ? (dout + BATCH * OUTD) : g_s1[inbuf ^ 1];
    float* s2out = last ? (dout + BATCH * OUTD + (size_t)BATCH * H) : g_s2[inbuf ^ 1];
    char* img1 = (char*)g_h1img + (size_t)blockIdx.x * ABLK;
    char* img2 = (char*)g_h2img + (size_t)blockIdx.x * ABLK;

    // warp tile: rows wm..wm+31, cols wn..wn+63
    const int wm = (wid & 3) * 32;
    const int wn = (wid >> 2) * 64;

    // cp.async both A images (64KB each; 128B per thread each) + first B chunk
#pragma unroll
    for (int q = 0; q < 8; q++) {
        int e = (q * NTHR + tid) * 16;
        cpasync16(sm + SM_A1 + e, img1 + e);
        cpasync16(sm + SM_A2 + e, img2 + e);
    }
    cpasync_commit();
    prefetch_chunk(sm, 0, tid, (const char*)g_B1, 0);

    // small staging (regular STS; covered by the kc=0 barrier)
    for (int i = tid; i < OUTD * H; i += NTHR) ((float*)(sm + SM_W0))[i] = W0[i];
    if (tid < OUTD)                            ((float*)(sm + SM_B0V))[tid] = b0[tid];
    for (int i = tid; i < MROWS * OUTD; i += NTHR)
        ((float*)(sm + SM_RS0))[i] = rho_f(s0in[row0 * OUTD + i]);

    float acc[2][8][4];

    for (int g = 0; g < 2; g++) {
        const char* img = g ? (const char*)g_B2e : (const char*)g_B1;
        const uint32_t abase = smb + (g ? SM_A2 : SM_A1);
        const int nchunks = g ? 9 : 8;

#pragma unroll
        for (int i = 0; i < 2; i++)
#pragma unroll
            for (int j = 0; j < 8; j++)
#pragma unroll
                for (int q = 0; q < 4; q++) acc[i][j][q] = 0.f;

#pragma unroll 1
        for (int kc = 0; kc < nchunks; kc++) {
            const int buf = kc & 1;
            cpasync_wait0();
            __syncthreads();
            if (kc < nchunks - 1)
                prefetch_chunk(sm, buf ^ 1, tid, img, kc + 1);
            else if (g == 0)
                prefetch_chunk(sm, buf ^ 1, tid, (const char*)g_B2e, 0);

            const uint32_t bbase = smb + SM_B + buf * 16384;

            if (g == 1 && kc == 8) {
                // fold chunk: A = [rs0 | 1 | 0] composed in regs (global k 256..271)
                const float* rs0 = (const float*)(sm + SM_RS0);
                const int t = lane & 3, gq = lane >> 2;
                uint32_t ae[2][4];
#pragma unroll
                for (int i = 0; i < 2; i++) {
                    int r0 = wm + i * 16 + gq, r1 = r0 + 8;
                    float v00 = rs0[r0 * OUTD + 2 * t], v01 = rs0[r0 * OUTD + 2 * t + 1];
                    float v10 = rs0[r1 * OUTD + 2 * t], v11 = rs0[r1 * OUTD + 2 * t + 1];
                    float v02, v03, v12, v13;
                    if (t == 0) {
                        v02 = rs0[r0 * OUTD + 8]; v03 = rs0[r0 * OUTD + 9];
                        v12 = rs0[r1 * OUTD + 8]; v13 = rs0[r1 * OUTD + 9];
                    } else if (t == 1) {
                        v02 = 1.f; v03 = 0.f; v12 = 1.f; v13 = 0.f;
                    } else {
                        v02 = v03 = v12 = v13 = 0.f;
                    }
                    ae[i][0] = pack_h2(v00, v01); ae[i][1] = pack_h2(v10, v11);
                    ae[i][2] = pack_h2(v02, v03); ae[i][3] = pack_h2(v12, v13);
                }
                const int kl = lane & 15;
#pragma unroll
                for (int jp = 0; jp < 4; jp++) {
                    int nch = ((wn + jp * 16) >> 3) + (lane >> 4);
                    uint32_t boff = (uint32_t)kl * 512u + ((uint32_t)(nch ^ (kl & 7)) << 4);
                    uint32_t bh[4];
                    ldsm_x4_t(bh, bbase + boff);
#pragma unroll
                    for (int h = 0; h < 2; h++)
#pragma unroll
                        for (int i = 0; i < 2; i++)
                            mma16816(acc[i][jp * 2 + h], ae[i], bh[2 * h], bh[2 * h + 1]);
                }
            } else {
#pragma unroll
                for (int ks = 0; ks < 2; ks++) {
                    const int kk = kc * 32 + ks * 16;
                    uint32_t ah[2][4];
#pragma unroll
                    for (int i = 0; i < 2; i++) {
                        int mr = wm + i * 16 + (lane & 15);
                        uint32_t aoff = (uint32_t)mr * 512u
                                      + ((uint32_t)(((kk >> 3) + (lane >> 4)) ^ (mr & 7)) << 4);
                        ldsm_x4(ah[i], abase + aoff);
                    }
                    const int kl = ks * 16 + (lane & 15);
#pragma unroll
                    for (int jp = 0; jp < 4; jp++) {
                        int nch = ((wn + jp * 16) >> 3) + (lane >> 4);
                        uint32_t boff = (uint32_t)kl * 512u
                                      + ((uint32_t)(nch ^ (kl & 7)) << 4);
                        uint32_t bh[4];
                        ldsm_x4_t(bh, bbase + boff);
#pragma unroll
                        for (int h = 0; h < 2; h++)
#pragma unroll
                            for (int i = 0; i < 2; i++)
                                mma16816(acc[i][jp * 2 + h], ah[i], bh[2 * h], bh[2 * h + 1]);
                    }
                }
            }
        }

        if (g == 0) {
            // ---- epilogue s2: s2' = rho(0.5*(s2 + rhop(s2)*(X + P2))); also emit fp16 image
#pragma unroll
            for (int i = 0; i < 2; i++) {
                int r = wm + i * 16 + (lane >> 2);
#pragma unroll
                for (int j = 0; j < 8; j++) {
                    int c = wn + j * 8 + 2 * (lane & 3);
#pragma unroll
                    for (int half = 0; half < 2; half++) {
                        int m = r + half * 8;
                        size_t gr = row0 + m;
                        float p0 = acc[i][j][half * 2], p1 = acc[i][j][half * 2 + 1];
                        float2 xo = *(const float2*)(g_X + gr * H + c);
                        float2 so = *(const float2*)(s2in + gr * H + c);
                        float2 ov;
                        ov.x = rho_f(0.5f * (so.x + ((so.x >= 0.f && so.x <= 1.f) ? (xo.x + p0) : 0.f)));
                        ov.y = rho_f(0.5f * (so.y + ((so.y >= 0.f && so.y <= 1.f) ? (xo.y + p1) : 0.f)));
                        *(float2*)(s2out + gr * H + c) = ov;
                        *(uint32_t*)(img2 + img_off(m, c)) = pack_h2(ov.x, ov.y);
                    }
                }
            }
            // ---- s0 update: warp-per-row, W0 in regs, shuffle reduce
            {
                const float* W0s = (const float*)(sm + SM_W0);
                const float* b0s = (const float*)(sm + SM_B0V);
                float4 wreg[OUTD][2];
#pragma unroll
                for (int o = 0; o < OUTD; o++) {
                    wreg[o][0] = *(const float4*)(W0s + o * H + lane * 8);
                    wreg[o][1] = *(const float4*)(W0s + o * H + lane * 8 + 4);
                }
#pragma unroll 1
                for (int rr = 0; rr < 8; rr++) {
                    int r = wid * 8 + rr;
                    const float* srow = s1in + (row0 + r) * H + lane * 8;
                    float4 v0 = *(const float4*)srow;
                    float4 v1 = *(const float4*)(srow + 4);
                    v0.x = rho_f(v0.x); v0.y = rho_f(v0.y); v0.z = rho_f(v0.z); v0.w = rho_f(v0.w);
                    v1.x = rho_f(v1.x); v1.y = rho_f(v1.y); v1.z = rho_f(v1.z); v1.w = rho_f(v1.w);
                    float accs[OUTD];
#pragma unroll
                    for (int o = 0; o < OUTD; o++) {
                        float4 w0 = wreg[o][0], w1 = wreg[o][1];
                        accs[o] = v0.x * w0.x + v0.y * w0.y + v0.z * w0.z + v0.w * w0.w
                                + v1.x * w1.x + v1.y * w1.y + v1.z * w1.z + v1.w * w1.w;
                    }
#pragma unroll
                    for (int d = 16; d; d >>= 1)
#pragma unroll
                        for (int o = 0; o < OUTD; o++)
                            accs[o] += __shfl_xor_sync(0xffffffffu, accs[o], d);
                    if (lane == 0) {
#pragma unroll
                        for (int o = 0; o < OUTD; o++) {
                            float s = s0in[(row0 + r) * OUTD + o];
                            s0out[(row0 + r) * OUTD + o] = rho_f(0.5f * (s + accs[o] + b0s[o]));
                        }
                    }
                }
            }
        } else {
            // ---- epilogue s1: pre = P1 (b2 + rho(s0)@W0 folded into GEMM); emit fp16 image
#pragma unroll
            for (int i = 0; i < 2; i++) {
                int r = wm + i * 16 + (lane >> 2);
#pragma unroll
                for (int j = 0; j < 8; j++) {
                    int c = wn + j * 8 + 2 * (lane & 3);
#pragma unroll
                    for (int half = 0; half < 2; half++) {
                        int m = r + half * 8;
                        size_t gr = row0 + m;
                        float p0 = acc[i][j][half * 2], p1 = acc[i][j][half * 2 + 1];
                        float2 so = *(const float2*)(s1in + gr * H + c);
                        float2 ov;
                        ov.x = rho_f(0.5f * (so.x + ((so.x >= 0.f && so.x <= 1.f) ? p0 : 0.f)));
                        ov.y = rho_f(0.5f * (so.y + ((so.y >= 0.f && so.y <= 1.f) ? p1 : 0.f)));
                        *(float2*)(s1out + gr * H + c) = ov;
                        *(uint32_t*)(img1 + img_off(m, c)) = pack_h2(ov.x, ov.y);
                    }
                }
            }
        }
    }
}

// ---------------- launch ----------------
extern "C" void kernel_launch(void* const* d_in, const int* in_sizes, int n_in,
                              void* d_out, int out_size)
{
    (void)in_sizes; (void)n_in; (void)out_size;
    const float* data = (const float*)d_in[0];
    const float* s0   = (const float*)d_in[1];
    const float* s1   = (const float*)d_in[2];
    const float* s2   = (const float*)d_in[3];
    const float* W0   = (const float*)d_in[4];
    const float* b0   = (const float*)d_in[5];
    const float* W2   = (const float*)d_in[6];
    const float* b2   = (const float*)d_in[7];
    const float* W4   = (const float*)d_in[8];
    const float* b4   = (const float*)d_in[9];
    float* out = (float*)d_out;

    cudaFuncSetAttribute(step_kernel, cudaFuncAttributeMaxDynamicSharedMemorySize, SM_TOTAL);

    init_kernel<<<(BATCH * H / 4) / 256, 256>>>(s0, s1, s2);
    img_kernel<<<H, H2>>>(W2, W0, b2);
    x_kernel<<<dim3(BATCH / 64, H / 64), 256>>>(data, W4, b4);
    for (int t = 0; t < TSTEPS; t++) {
        step_kernel<<<BATCH / MROWS, NTHR, SM_TOTAL>>>(
            t & 1, t == TSTEPS - 1, out, W0, b0);
    }
}

// round 14
// speedup vs baseline: 1.4451x; 1.4451x over previous
#include <cuda_runtime.h>
#include <cuda_fp16.h>
#include <cstdint>

#define BATCH 16384
#define H 256
#define H2 288
#define OUTD 10
#define IND 784
#define TSTEPS 50
#define MROWS 128
#define NTHR 512

typedef unsigned long long ull;

// -------- device scratch --------
__device__ float g_X[BATCH * H];
__device__ float g_s0[2][BATCH * OUTD];
__device__ float g_s1[2][BATCH * H];
__device__ float g_s2[2][BATCH * H];
// fp16 weight images in [k][n] layout (n contiguous), XOR-swizzled 16B chunks.
// B1[k][n] = W2[k][n]  (P2 = rho(s1) @ W2)
// B2e: rows 0..255 = W2[n][k] (P1 = rho(s2) @ W2^T); rows 256+o = W0[o][n];
//      row 266 = b2[n]; rows 267..287 = 0   (extra chunk folds b2 + rho(s0)@W0)
__device__ __half g_B1[H * H], g_B2e[H2 * H];

__device__ __forceinline__ float rho_f(float x) { return fminf(fmaxf(x, 0.0f), 1.0f); }

__device__ __forceinline__ ull pack2(float a, float b) {
    ull r; asm("mov.b64 %0, {%1, %2};" : "=l"(r) : "f"(a), "f"(b)); return r;
}
__device__ __forceinline__ void fma2(ull &d, ull a, ull b) {
    asm("fma.rn.f32x2 %0, %1, %2, %0;" : "+l"(d) : "l"(a), "l"(b));
}
__device__ __forceinline__ float2 unpack2(ull v) {
    float2 f; asm("mov.b64 {%0, %1}, %2;" : "=f"(f.x), "=f"(f.y) : "l"(v)); return f;
}
__device__ __forceinline__ void cpasync16(char* dst, const char* src) {
    unsigned d = (unsigned)__cvta_generic_to_shared(dst);
    asm volatile("cp.async.cg.shared.global [%0], [%1], 16;" :: "r"(d), "l"(src));
}
__device__ __forceinline__ void cpasync_commit() { asm volatile("cp.async.commit_group;"); }
__device__ __forceinline__ void cpasync_wait0()  { asm volatile("cp.async.wait_group 0;"); }

__device__ __forceinline__ uint32_t smem_u32(const void* p) {
    uint32_t a;
    asm("{ .reg .u64 t; cvta.to.shared.u64 t, %1; cvt.u32.u64 %0, t; }" : "=r"(a) : "l"(p));
    return a;
}
__device__ __forceinline__ void ldsm_x4(uint32_t* r, uint32_t addr) {
    asm volatile("ldmatrix.sync.aligned.m8n8.x4.shared.b16 {%0,%1,%2,%3}, [%4];"
                 : "=r"(r[0]), "=r"(r[1]), "=r"(r[2]), "=r"(r[3]) : "r"(addr));
}
__device__ __forceinline__ void ldsm_x4_t(uint32_t* r, uint32_t addr) {
    asm volatile("ldmatrix.sync.aligned.m8n8.x4.trans.shared.b16 {%0,%1,%2,%3}, [%4];"
                 : "=r"(r[0]), "=r"(r[1]), "=r"(r[2]), "=r"(r[3]) : "r"(addr));
}
__device__ __forceinline__ void mma16816(float* c, const uint32_t* a, uint32_t b0, uint32_t b1) {
    asm volatile("mma.sync.aligned.m16n8k16.row.col.f32.f16.f16.f32 "
        "{%0,%1,%2,%3}, {%4,%5,%6,%7}, {%8,%9}, {%0,%1,%2,%3};"
        : "+f"(c[0]), "+f"(c[1]), "+f"(c[2]), "+f"(c[3])
        : "r"(a[0]), "r"(a[1]), "r"(a[2]), "r"(a[3]), "r"(b0), "r"(b1));
}
__device__ __forceinline__ uint32_t pack_h2(float a, float b) {
    __half ha = __float2half(a), hb = __float2half(b);
    return ((uint32_t)__half_as_ushort(hb) << 16) | __half_as_ushort(ha);
}

// ---------------- init ----------------
__global__ void __launch_bounds__(256) init_kernel(
    const float* __restrict__ s0, const float* __restrict__ s1,
    const float* __restrict__ s2)
{
    int idx = blockIdx.x * 256 + threadIdx.x;
    ((float4*)g_s1[0])[idx] = ((const float4*)s1)[idx];
    ((float4*)g_s2[0])[idx] = ((const float4*)s2)[idx];
    if (idx < BATCH * OUTD / 4)
        ((float4*)g_s0[0])[idx] = ((const float4*)s0)[idx];
}

// ---------------- build fp16 weight images, [k][n] layout, swizzled ----------------
// element (k, n) at byte: k*512 + (((n>>3) ^ (k&7)) << 4) + (n&7)*2
__global__ void __launch_bounds__(H2) img_kernel(
    const float* __restrict__ W2, const float* __restrict__ W0,
    const float* __restrict__ b2)
{
    int n = blockIdx.x, k = threadIdx.x;
    uint32_t off = (uint32_t)k * 512u + ((((uint32_t)n >> 3) ^ ((uint32_t)k & 7u)) << 4)
                 + ((uint32_t)n & 7u) * 2u;
    if (k < H)
        *(__half*)((char*)g_B1 + off) = __float2half(W2[k * H + n]);
    float w;
    if (k < H)              w = W2[n * H + k];
    else if (k < H + OUTD)  w = W0[(k - H) * H + n];
    else if (k == H + OUTD) w = b2[n];
    else                    w = 0.f;
    *(__half*)((char*)g_B2e + off) = __float2half(w);
}

// ---------------- prefix: X = rho(data) @ W4.T + b4 (fp32, once) ----------------
__global__ void __launch_bounds__(256) x_kernel(
    const float* __restrict__ data, const float* __restrict__ W4,
    const float* __restrict__ b4)
{
    __shared__ float As[16 * 66];
    __shared__ float Bs[16 * 66];
    const int tid = threadIdx.x;
    const int i0 = blockIdx.x * 64, j0 = blockIdx.y * 64;
    const int tx = tid & 15, ty = tid >> 4;
    const int kk = tid & 15, rr = tid >> 4;

    ull acc[4][2] = {};
    for (int k0 = 0; k0 < IND; k0 += 16) {
#pragma unroll
        for (int q = 0; q < 4; q++) {
            int r = rr + q * 16;
            As[kk * 66 + r] = rho_f(data[(size_t)(i0 + r) * IND + k0 + kk]);
            Bs[kk * 66 + r] = W4[(size_t)(j0 + r) * IND + k0 + kk];
        }
        __syncthreads();
#pragma unroll
        for (int k = 0; k < 16; k++) {
            ull a[4];
#pragma unroll
            for (int i = 0; i < 4; i++) {
                float av = As[k * 66 + ty * 4 + i];
                a[i] = pack2(av, av);
            }
            ull w0 = *(const ull*)(Bs + k * 66 + tx * 2);
            ull w1 = *(const ull*)(Bs + k * 66 + 32 + tx * 2);
#pragma unroll
            for (int i = 0; i < 4; i++) { fma2(acc[i][0], a[i], w0); fma2(acc[i][1], a[i], w1); }
        }
        __syncthreads();
    }
#pragma unroll
    for (int i = 0; i < 4; i++) {
        size_t row = (size_t)i0 + ty * 4 + i;
        float2 p0 = unpack2(acc[i][0]), p1 = unpack2(acc[i][1]);
        int j0a = j0 + tx * 2, j0b = j0 + 32 + tx * 2;
        *(float2*)(g_X + row * H + j0a) = make_float2(p0.x + b4[j0a], p0.y + b4[j0a + 1]);
        *(float2*)(g_X + row * H + j0b) = make_float2(p1.x + b4[j0b], p1.y + b4[j0b + 1]);
    }
}

// ---------------- SMEM layout (bytes) ----------------
#define SM_A1   0                      // [128][256] fp16 swizzled = 64KB  (rho(s1))
#define SM_A2   65536                  // 64KB (rho(s2))
#define SM_B    131072                 // 2 bufs x 16KB = 32KB
#define SM_W0   163840                 // [10][256] f32
#define SM_RS0  174080                 // [128][10] f32
#define SM_B0V  179200
#define SM_TOTAL (SM_B0V + 64)

// stage state [128][256] as fp16 in swizzled row-major layout (state already in [0,1])
// element (m, k) at byte: m*512 + (((k>>3) ^ (m&7)) << 4) + (k&7)*2
__device__ __forceinline__ void stage_A(const float* __restrict__ sin, size_t row0,
                                        char* smA, int tid)
{
#pragma unroll
    for (int it = 0; it < 8; it++) {
        int idx = it * NTHR + tid;
        int m = idx >> 5, ch = idx & 31, k = ch << 3;
        float4 v0 = *(const float4*)(sin + (row0 + m) * H + k);
        float4 v1 = *(const float4*)(sin + (row0 + m) * H + k + 4);
        uint32_t h[4];
        h[0] = pack_h2(v0.x, v0.y); h[1] = pack_h2(v0.z, v0.w);
        h[2] = pack_h2(v1.x, v1.y); h[3] = pack_h2(v1.z, v1.w);
        uint32_t off = (uint32_t)m * 512u + (((uint32_t)(ch ^ (m & 7))) << 4);
        *(uint4*)(smA + off) = make_uint4(h[0], h[1], h[2], h[3]);
    }
}

// prefetch one 32-k-row weight chunk (16KB) into buffer buf
__device__ __forceinline__ void prefetch_chunk(char* sm, int buf, int tid,
                                               const char* img, int chunk)
{
    char* d = sm + SM_B + buf * 16384 + tid * 32;
    const char* s = img + (size_t)chunk * 16384 + tid * 32;
    cpasync16(d, s); cpasync16(d + 16, s + 16);
    cpasync_commit();
}

__global__ void __launch_bounds__(NTHR, 1) step_kernel(
    int inbuf, int last, float* __restrict__ dout,
    const float* __restrict__ W0, const float* __restrict__ b0)
{
    extern __shared__ char sm[];
    const uint32_t smb = smem_u32(sm);
    const int tid = threadIdx.x;
    const int lane = tid & 31, wid = tid >> 5;
    const size_t row0 = (size_t)blockIdx.x * MROWS;

    const float* __restrict__ s0in = g_s0[inbuf];
    const float* __restrict__ s1in = g_s1[inbuf];
    const float* __restrict__ s2in = g_s2[inbuf];
    float* s0out = last ? dout : g_s0[inbuf ^ 1];
    float* s1out = last ? (dout + BATCH * OUTD) : g_s1[inbuf ^ 1];
    float* s2out = last ? (dout + BATCH * OUTD + (size_t)BATCH * H) : g_s2[inbuf ^ 1];

    // warp tile: rows wm..wm+31, cols wn..wn+63
    const int wm = (wid & 3) * 32;
    const int wn = (wid >> 2) * 64;

    // small staging
    for (int i = tid; i < OUTD * H; i += NTHR) ((float*)(sm + SM_W0))[i] = W0[i];
    if (tid < OUTD)                            ((float*)(sm + SM_B0V))[tid] = b0[tid];
    for (int i = tid; i < MROWS * OUTD; i += NTHR)
        ((float*)(sm + SM_RS0))[i] = s0in[row0 * OUTD + i];   // state in [0,1]: rho = id
    // both A tiles upfront
    stage_A(s1in, row0, sm + SM_A1, tid);
    stage_A(s2in, row0, sm + SM_A2, tid);
    prefetch_chunk(sm, 0, tid, (const char*)g_B1, 0);
    __syncthreads();

    float acc[2][8][4];

    for (int g = 0; g < 2; g++) {
        const char* img = g ? (const char*)g_B2e : (const char*)g_B1;
        const uint32_t abase = smb + (g ? SM_A2 : SM_A1);
        const int nchunks = g ? 9 : 8;

#pragma unroll
        for (int i = 0; i < 2; i++)
#pragma unroll
            for (int j = 0; j < 8; j++)
#pragma unroll
                for (int q = 0; q < 4; q++) acc[i][j][q] = 0.f;

#pragma unroll 1
        for (int kc = 0; kc < nchunks; kc++) {
            const int buf = kc & 1;
            cpasync_wait0();
            __syncthreads();
            if (kc < nchunks - 1)
                prefetch_chunk(sm, buf ^ 1, tid, img, kc + 1);
            else if (g == 0)
                prefetch_chunk(sm, buf ^ 1, tid, (const char*)g_B2e, 0);

            const uint32_t bbase = smb + SM_B + buf * 16384;

            if (g == 1 && kc == 8) {
                // fold chunk: A = [rs0 | 1 | 0] composed in regs (global k 256..271)
                const float* rs0 = (const float*)(sm + SM_RS0);
                const int t = lane & 3, gq = lane >> 2;
                uint32_t ae[2][4];
#pragma unroll
                for (int i = 0; i < 2; i++) {
                    int r0 = wm + i * 16 + gq, r1 = r0 + 8;
                    float v00 = rs0[r0 * OUTD + 2 * t], v01 = rs0[r0 * OUTD + 2 * t + 1];
                    float v10 = rs0[r1 * OUTD + 2 * t], v11 = rs0[r1 * OUTD + 2 * t + 1];
                    float v02, v03, v12, v13;
                    if (t == 0) {
                        v02 = rs0[r0 * OUTD + 8]; v03 = rs0[r0 * OUTD + 9];
                        v12 = rs0[r1 * OUTD + 8]; v13 = rs0[r1 * OUTD + 9];
                    } else if (t == 1) {
                        v02 = 1.f; v03 = 0.f; v12 = 1.f; v13 = 0.f;
                    } else {
                        v02 = v03 = v12 = v13 = 0.f;
                    }
                    ae[i][0] = pack_h2(v00, v01); ae[i][1] = pack_h2(v10, v11);
                    ae[i][2] = pack_h2(v02, v03); ae[i][3] = pack_h2(v12, v13);
                }
                const int kl = lane & 15;
#pragma unroll
                for (int jp = 0; jp < 4; jp++) {
                    int nch = ((wn + jp * 16) >> 3) + (lane >> 4);
                    uint32_t boff = (uint32_t)kl * 512u + ((uint32_t)(nch ^ (kl & 7)) << 4);
                    uint32_t bh[4];
                    ldsm_x4_t(bh, bbase + boff);
#pragma unroll
                    for (int h = 0; h < 2; h++)
#pragma unroll
                        for (int i = 0; i < 2; i++)
                            mma16816(acc[i][jp * 2 + h], ae[i], bh[2 * h], bh[2 * h + 1]);
                }
            } else {
#pragma unroll
                for (int ks = 0; ks < 2; ks++) {
                    const int kk = kc * 32 + ks * 16;
                    uint32_t ah[2][4];
#pragma unroll
                    for (int i = 0; i < 2; i++) {
                        int mr = wm + i * 16 + (lane & 15);
                        uint32_t aoff = (uint32_t)mr * 512u
                                      + ((uint32_t)(((kk >> 3) + (lane >> 4)) ^ (mr & 7)) << 4);
                        ldsm_x4(ah[i], abase + aoff);
                    }
                    const int kl = ks * 16 + (lane & 15);
#pragma unroll
                    for (int jp = 0; jp < 4; jp++) {
                        int nch = ((wn + jp * 16) >> 3) + (lane >> 4);
                        uint32_t boff = (uint32_t)kl * 512u
                                      + ((uint32_t)(nch ^ (kl & 7)) << 4);
                        uint32_t bh[4];
                        ldsm_x4_t(bh, bbase + boff);
#pragma unroll
                        for (int h = 0; h < 2; h++)
#pragma unroll
                            for (int i = 0; i < 2; i++)
                                mma16816(acc[i][jp * 2 + h], ah[i], bh[2 * h], bh[2 * h + 1]);
                    }
                }
            }
        }

        if (g == 0) {
            // ---- epilogue s2: s2' = clip(0.5*(s2 + X + P2))  (gate always true)
#pragma unroll
            for (int i = 0; i < 2; i++) {
                int r = wm + i * 16 + (lane >> 2);
#pragma unroll
                for (int j = 0; j < 8; j++) {
                    int c = wn + j * 8 + 2 * (lane & 3);
#pragma unroll
                    for (int half = 0; half < 2; half++) {
                        size_t gr = row0 + r + half * 8;
                        float p0 = acc[i][j][half * 2], p1 = acc[i][j][half * 2 + 1];
                        float2 xo = *(const float2*)(g_X + gr * H + c);
                        float2 so = *(const float2*)(s2in + gr * H + c);
                        float2 ov;
                        ov.x = rho_f(0.5f * (so.x + xo.x + p0));
                        ov.y = rho_f(0.5f * (so.y + xo.y + p1));
                        *(float2*)(s2out + gr * H + c) = ov;
                    }
                }
            }
            // ---- s0 update: warp-per-row; rho(s1) read from fp16 smem image (conflict-free)
            {
                const float* W0s = (const float*)(sm + SM_W0);
                const float* b0s = (const float*)(sm + SM_B0V);
                float4 wreg[OUTD][2];
#pragma unroll
                for (int o = 0; o < OUTD; o++) {
                    wreg[o][0] = *(const float4*)(W0s + o * H + lane * 8);
                    wreg[o][1] = *(const float4*)(W0s + o * H + lane * 8 + 4);
                }
#pragma unroll 1
                for (int rr = 0; rr < 8; rr++) {
                    int r = wid * 8 + rr;
                    // fp16 image: element (r, lane*8) at r*512 + ((lane ^ (r&7)) << 4)
                    uint32_t aoff = (uint32_t)r * 512u + (((uint32_t)(lane ^ (r & 7))) << 4);
                    uint4 hv = *(const uint4*)(sm + SM_A1 + aoff);
                    float2 f0 = __half22float2(*(__half2*)&hv.x);
                    float2 f1 = __half22float2(*(__half2*)&hv.y);
                    float2 f2 = __half22float2(*(__half2*)&hv.z);
                    float2 f3 = __half22float2(*(__half2*)&hv.w);
                    float accs[OUTD];
#pragma unroll
                    for (int o = 0; o < OUTD; o++) {
                        float4 w0 = wreg[o][0], w1 = wreg[o][1];
                        accs[o] = f0.x * w0.x + f0.y * w0.y + f1.x * w0.z + f1.y * w0.w
                                + f2.x * w1.x + f2.y * w1.y + f3.x * w1.z + f3.y * w1.w;
                    }
#pragma unroll
                    for (int d = 16; d; d >>= 1)
#pragma unroll
                        for (int o = 0; o < OUTD; o++)
                            accs[o] += __shfl_xor_sync(0xffffffffu, accs[o], d);
                    if (lane == 0) {
#pragma unroll
                        for (int o = 0; o < OUTD; o++) {
                            float s = s0in[(row0 + r) * OUTD + o];
                            s0out[(row0 + r) * OUTD + o] = rho_f(0.5f * (s + accs[o] + b0s[o]));
                        }
                    }
                }
            }
        } else {
            // ---- epilogue s1: s1' = clip(0.5*(s1 + P1))  (bias+W0 folded; gate always true)
#pragma unroll
            for (int i = 0; i < 2; i++) {
                int r = wm + i * 16 + (lane >> 2);
#pragma unroll
                for (int j = 0; j < 8; j++) {
                    int c = wn + j * 8 + 2 * (lane & 3);
#pragma unroll
                    for (int half = 0; half < 2; half++) {
                        size_t gr = row0 + r + half * 8;
                        float p0 = acc[i][j][half * 2], p1 = acc[i][j][half * 2 + 1];
                        float2 so = *(const float2*)(s1in + gr * H + c);
                        float2 ov;
                        ov.x = rho_f(0.5f * (so.x + p0));
                        ov.y = rho_f(0.5f * (so.y + p1));
                        *(float2*)(s1out + gr * H + c) = ov;
                    }
                }
            }
        }
    }
}

// ---------------- launch ----------------
extern "C" void kernel_launch(void* const* d_in, const int* in_sizes, int n_in,
                              void* d_out, int out_size)
{
    (void)in_sizes; (void)n_in; (void)out_size;
    const float* data = (const float*)d_in[0];
    const float* s0   = (const float*)d_in[1];
    const float* s1   = (const float*)d_in[2];
    const float* s2   = (const float*)d_in[3];
    const float* W0   = (const float*)d_in[4];
    const float* b0   = (const float*)d_in[5];
    const float* W2   = (const float*)d_in[6];
    const float* b2   = (const float*)d_in[7];
    const float* W4   = (const float*)d_in[8];
    const float* b4   = (const float*)d_in[9];
    float* out = (float*)d_out;

    cudaFuncSetAttribute(step_kernel, cudaFuncAttributeMaxDynamicSharedMemorySize, SM_TOTAL);

    init_kernel<<<(BATCH * H / 4) / 256, 256>>>(s0, s1, s2);
    img_kernel<<<H, H2>>>(W2, W0, b2);
    x_kernel<<<dim3(BATCH / 64, H / 64), 256>>>(data, W4, b4);
    for (int t = 0; t < TSTEPS; t++) {
        step_kernel<<<BATCH / MROWS, NTHR, SM_TOTAL>>>(
            t & 1, t == TSTEPS - 1, out, W0, b0);
    }
}

// round 15
// speedup vs baseline: 1.5426x; 1.0675x over previous
#include <cuda_runtime.h>
#include <cuda_fp16.h>
#include <cstdint>

#define BATCH 16384
#define H 256
#define H2 288
#define OUTD 10
#define IND 784
#define TSTEPS 50
#define MROWS 128
#define NTHR 512

typedef unsigned long long ull;

// -------- device scratch --------
__device__ float g_X[BATCH * H];
__device__ float g_s0[2][BATCH * OUTD];
__device__ float g_s1[2][BATCH * H];
__device__ float g_s2[2][BATCH * H];
// fp16 weight images in [k][n] layout (n contiguous), XOR-swizzled 16B chunks.
// B1[k][n] = W2[k][n]  (P2 = rho(s1) @ W2)
// B2e: rows 0..255 = W2[n][k] (P1 = rho(s2) @ W2^T); rows 256+o = W0[o][n];
//      row 266 = b2[n]; rows 267..287 = 0   (chunk 16 folds b2 + rho(s0)@W0)
__device__ __half g_B1[H * H], g_B2e[H2 * H];

__device__ __forceinline__ float rho_f(float x) { return fminf(fmaxf(x, 0.0f), 1.0f); }

__device__ __forceinline__ ull pack2(float a, float b) {
    ull r; asm("mov.b64 %0, {%1, %2};" : "=l"(r) : "f"(a), "f"(b)); return r;
}
__device__ __forceinline__ void fma2(ull &d, ull a, ull b) {
    asm("fma.rn.f32x2 %0, %1, %2, %0;" : "+l"(d) : "l"(a), "l"(b));
}
__device__ __forceinline__ float2 unpack2(ull v) {
    float2 f; asm("mov.b64 {%0, %1}, %2;" : "=f"(f.x), "=f"(f.y) : "l"(v)); return f;
}
__device__ __forceinline__ void cpasync16(char* dst, const char* src) {
    unsigned d = (unsigned)__cvta_generic_to_shared(dst);
    asm volatile("cp.async.cg.shared.global [%0], [%1], 16;" :: "r"(d), "l"(src));
}
__device__ __forceinline__ void cpasync_commit() { asm volatile("cp.async.commit_group;"); }
__device__ __forceinline__ void cpasync_wait0()  { asm volatile("cp.async.wait_group 0;"); }

__device__ __forceinline__ uint32_t smem_u32(const void* p) {
    uint32_t a;
    asm("{ .reg .u64 t; cvta.to.shared.u64 t, %1; cvt.u32.u64 %0, t; }" : "=r"(a) : "l"(p));
    return a;
}
__device__ __forceinline__ void ldsm_x4(uint32_t* r, uint32_t addr) {
    asm volatile("ldmatrix.sync.aligned.m8n8.x4.shared.b16 {%0,%1,%2,%3}, [%4];"
                 : "=r"(r[0]), "=r"(r[1]), "=r"(r[2]), "=r"(r[3]) : "r"(addr));
}
__device__ __forceinline__ void ldsm_x4_t(uint32_t* r, uint32_t addr) {
    asm volatile("ldmatrix.sync.aligned.m8n8.x4.trans.shared.b16 {%0,%1,%2,%3}, [%4];"
                 : "=r"(r[0]), "=r"(r[1]), "=r"(r[2]), "=r"(r[3]) : "r"(addr));
}
__device__ __forceinline__ void mma16816(float* c, const uint32_t* a, uint32_t b0, uint32_t b1) {
    asm volatile("mma.sync.aligned.m16n8k16.row.col.f32.f16.f16.f32 "
        "{%0,%1,%2,%3}, {%4,%5,%6,%7}, {%8,%9}, {%0,%1,%2,%3};"
        : "+f"(c[0]), "+f"(c[1]), "+f"(c[2]), "+f"(c[3])
        : "r"(a[0]), "r"(a[1]), "r"(a[2]), "r"(a[3]), "r"(b0), "r"(b1));
}
__device__ __forceinline__ uint32_t pack_h2(float a, float b) {
    __half ha = __float2half(a), hb = __float2half(b);
    return ((uint32_t)__half_as_ushort(hb) << 16) | __half_as_ushort(ha);
}
// byte offset of element (m, k) in a 128x256 swizzled fp16 image
__device__ __forceinline__ uint32_t img_off(int m, int k) {
    return (uint32_t)m * 512u + ((((uint32_t)k >> 3) ^ ((uint32_t)m & 7u)) << 4)
         + ((uint32_t)k & 7u) * 2u;
}

// ---------------- build fp16 weight images ----------------
__global__ void __launch_bounds__(H2) img_kernel(
    const float* __restrict__ W2, const float* __restrict__ W0,
    const float* __restrict__ b2)
{
    int n = blockIdx.x, k = threadIdx.x;
    uint32_t off = (uint32_t)k * 512u + ((((uint32_t)n >> 3) ^ ((uint32_t)k & 7u)) << 4)
                 + ((uint32_t)n & 7u) * 2u;
    if (k < H)
        *(__half*)((char*)g_B1 + off) = __float2half(W2[k * H + n]);
    float w;
    if (k < H)              w = W2[n * H + k];
    else if (k < H + OUTD)  w = W0[(k - H) * H + n];
    else if (k == H + OUTD) w = b2[n];
    else                    w = 0.f;
    *(__half*)((char*)g_B2e + off) = __float2half(w);
}

// ---------------- prefix: X = rho(data) @ W4.T + b4 (fp32, once) ----------------
__global__ void __launch_bounds__(256) x_kernel(
    const float* __restrict__ data, const float* __restrict__ W4,
    const float* __restrict__ b4)
{
    __shared__ float As[16 * 66];
    __shared__ float Bs[16 * 66];
    const int tid = threadIdx.x;
    const int i0 = blockIdx.x * 64, j0 = blockIdx.y * 64;
    const int tx = tid & 15, ty = tid >> 4;
    const int kk = tid & 15, rr = tid >> 4;

    ull acc[4][2] = {};
    for (int k0 = 0; k0 < IND; k0 += 16) {
#pragma unroll
        for (int q = 0; q < 4; q++) {
            int r = rr + q * 16;
            As[kk * 66 + r] = rho_f(data[(size_t)(i0 + r) * IND + k0 + kk]);
            Bs[kk * 66 + r] = W4[(size_t)(j0 + r) * IND + k0 + kk];
        }
        __syncthreads();
#pragma unroll
        for (int k = 0; k < 16; k++) {
            ull a[4];
#pragma unroll
            for (int i = 0; i < 4; i++) {
                float av = As[k * 66 + ty * 4 + i];
                a[i] = pack2(av, av);
            }
            ull w0 = *(const ull*)(Bs + k * 66 + tx * 2);
            ull w1 = *(const ull*)(Bs + k * 66 + 32 + tx * 2);
#pragma unroll
            for (int i = 0; i < 4; i++) { fma2(acc[i][0], a[i], w0); fma2(acc[i][1], a[i], w1); }
        }
        __syncthreads();
    }
#pragma unroll
    for (int i = 0; i < 4; i++) {
        size_t row = (size_t)i0 + ty * 4 + i;
        float2 p0 = unpack2(acc[i][0]), p1 = unpack2(acc[i][1]);
        int j0a = j0 + tx * 2, j0b = j0 + 32 + tx * 2;
        *(float2*)(g_X + row * H + j0a) = make_float2(p0.x + b4[j0a], p0.y + b4[j0a + 1]);
        *(float2*)(g_X + row * H + j0b) = make_float2(p1.x + b4[j0b], p1.y + b4[j0b + 1]);
    }
}

// ---------------- SMEM layout (bytes) ----------------
#define SM_A1   0                      // [128][256] fp16 swizzled, persistent (rho(s1))
#define SM_A2   65536                  // 2 x 64KB double-buffered (rho(s2))
#define SM_B    196608                 // 2 bufs x 8KB (16 k-rows each)
#define SM_W0   212992                 // [10][256] f32
#define SM_RS0  223232                 // [128][10] f32
#define SM_B0V  228352
#define SM_TOTAL (SM_B0V + 64)

// initial stage: state [128][256] -> fp16 swizzled image (state in [0,1])
__device__ __forceinline__ void stage_A(const float* __restrict__ sin, size_t row0,
                                        char* smA, int tid)
{
#pragma unroll
    for (int it = 0; it < 8; it++) {
        int idx = it * NTHR + tid;
        int m = idx >> 5, ch = idx & 31, k = ch << 3;
        float4 v0 = *(const float4*)(sin + (row0 + m) * H + k);
        float4 v1 = *(const float4*)(sin + (row0 + m) * H + k + 4);
        uint32_t h[4];
        h[0] = pack_h2(v0.x, v0.y); h[1] = pack_h2(v0.z, v0.w);
        h[2] = pack_h2(v1.x, v1.y); h[3] = pack_h2(v1.z, v1.w);
        uint32_t off = (uint32_t)m * 512u + (((uint32_t)(ch ^ (m & 7))) << 4);
        *(uint4*)(smA + off) = make_uint4(h[0], h[1], h[2], h[3]);
    }
}

// prefetch one 16-k-row weight chunk (8KB) into buffer buf
__device__ __forceinline__ void prefetch_chunk(char* sm, int buf, int tid,
                                               const char* img, int chunk)
{
    cpasync16(sm + SM_B + buf * 8192 + tid * 16,
              img + (size_t)chunk * 8192 + tid * 16);
    cpasync_commit();
}

__global__ void __launch_bounds__(NTHR, 1) step_persist(
    const float* __restrict__ s0a, const float* __restrict__ s1a,
    const float* __restrict__ s2a, float* __restrict__ dout,
    const float* __restrict__ W0, const float* __restrict__ b0)
{
    extern __shared__ char sm[];
    const uint32_t smb = smem_u32(sm);
    const int tid = threadIdx.x;
    const int lane = tid & 31, wid = tid >> 5;
    const size_t row0 = (size_t)blockIdx.x * MROWS;

    const int wm = (wid & 3) * 32;
    const int wn = (wid >> 2) * 64;

    // one-time staging
    for (int i = tid; i < OUTD * H; i += NTHR) ((float*)(sm + SM_W0))[i] = W0[i];
    if (tid < OUTD)                            ((float*)(sm + SM_B0V))[tid] = b0[tid];
    stage_A(s1a, row0, sm + SM_A1, tid);
    stage_A(s2a, row0, sm + SM_A2, tid);
    prefetch_chunk(sm, 0, tid, (const char*)g_B1, 0);
    __syncthreads();

    int cur = 0;   // active A2 buffer
    int pb = 0;    // rotating B buffer parity
    float acc[2][8][4];

#pragma unroll 1
    for (int t = 0; t < TSTEPS; t++) {
        const int last = (t == TSTEPS - 1);
        const float* s0in = (t == 0) ? s0a : g_s0[(t - 1) & 1];
        const float* s1in = (t == 0) ? s1a : g_s1[(t - 1) & 1];
        const float* s2in = (t == 0) ? s2a : g_s2[(t - 1) & 1];
        float* s0out = last ? dout : g_s0[t & 1];
        float* s1out = last ? (dout + BATCH * OUTD) : g_s1[t & 1];
        float* s2out = last ? (dout + BATCH * OUTD + (size_t)BATCH * H) : g_s2[t & 1];

        // rs0 (s0 in [0,1]: rho = id). Prev step's fold reads finished (end-of-step sync).
        for (int i = tid; i < MROWS * OUTD; i += NTHR)
            ((float*)(sm + SM_RS0))[i] = s0in[row0 * OUTD + i];

#pragma unroll 1
        for (int g = 0; g < 2; g++) {
            const char* img = g ? (const char*)g_B2e : (const char*)g_B1;
            const uint32_t abase = smb + (g ? (SM_A2 + cur * 65536) : SM_A1);
            const int nchunks = g ? 17 : 16;

#pragma unroll
            for (int i = 0; i < 2; i++)
#pragma unroll
                for (int j = 0; j < 8; j++)
#pragma unroll
                    for (int q = 0; q < 4; q++) acc[i][j][q] = 0.f;

#pragma unroll 1
            for (int kc = 0; kc < nchunks; kc++) {
                const int buf = pb;
                cpasync_wait0();
                __syncthreads();
                if (kc < nchunks - 1)
                    prefetch_chunk(sm, buf ^ 1, tid, img, kc + 1);
                else if (g == 0)
                    prefetch_chunk(sm, buf ^ 1, tid, (const char*)g_B2e, 0);
                else
                    prefetch_chunk(sm, buf ^ 1, tid, (const char*)g_B1, 0); // next step
                pb ^= 1;

                const uint32_t bbase = smb + SM_B + buf * 8192;

                if (g == 1 && kc == 16) {
                    // fold chunk: A = [rs0 | 1 | 0] composed in regs (global k 256..271)
                    const float* rs0 = (const float*)(sm + SM_RS0);
                    const int tq = lane & 3, gq = lane >> 2;
                    uint32_t ae[2][4];
#pragma unroll
                    for (int i = 0; i < 2; i++) {
                        int r0 = wm + i * 16 + gq, r1 = r0 + 8;
                        float v00 = rs0[r0 * OUTD + 2 * tq], v01 = rs0[r0 * OUTD + 2 * tq + 1];
                        float v10 = rs0[r1 * OUTD + 2 * tq], v11 = rs0[r1 * OUTD + 2 * tq + 1];
                        float v02, v03, v12, v13;
                        if (tq == 0) {
                            v02 = rs0[r0 * OUTD + 8]; v03 = rs0[r0 * OUTD + 9];
                            v12 = rs0[r1 * OUTD + 8]; v13 = rs0[r1 * OUTD + 9];
                        } else if (tq == 1) {
                            v02 = 1.f; v03 = 0.f; v12 = 1.f; v13 = 0.f;
                        } else {
                            v02 = v03 = v12 = v13 = 0.f;
                        }
                        ae[i][0] = pack_h2(v00, v01); ae[i][1] = pack_h2(v10, v11);
                        ae[i][2] = pack_h2(v02, v03); ae[i][3] = pack_h2(v12, v13);
                    }
                    const int kl = lane & 15;
#pragma unroll
                    for (int jp = 0; jp < 4; jp++) {
                        int nch = ((wn + jp * 16) >> 3) + (lane >> 4);
                        uint32_t boff = (uint32_t)kl * 512u + ((uint32_t)(nch ^ (kl & 7)) << 4);
                        uint32_t bh[4];
                        ldsm_x4_t(bh, bbase + boff);
#pragma unroll
                        for (int h = 0; h < 2; h++)
#pragma unroll
                            for (int i = 0; i < 2; i++)
                                mma16816(acc[i][jp * 2 + h], ae[i], bh[2 * h], bh[2 * h + 1]);
                    }
                } else {
                    const int kk = kc * 16;
                    uint32_t ah[2][4];
#pragma unroll
                    for (int i = 0; i < 2; i++) {
                        int mr = wm + i * 16 + (lane & 15);
                        uint32_t aoff = (uint32_t)mr * 512u
                                      + ((uint32_t)(((kk >> 3) + (lane >> 4)) ^ (mr & 7)) << 4);
                        ldsm_x4(ah[i], abase + aoff);
                    }
                    const int kl = lane & 15;
#pragma unroll
                    for (int jp = 0; jp < 4; jp++) {
                        int nch = ((wn + jp * 16) >> 3) + (lane >> 4);
                        uint32_t boff = (uint32_t)kl * 512u
                                      + ((uint32_t)(nch ^ (kl & 7)) << 4);
                        uint32_t bh[4];
                        ldsm_x4_t(bh, bbase + boff);
#pragma unroll
                        for (int h = 0; h < 2; h++)
#pragma unroll
                            for (int i = 0; i < 2; i++)
                                mma16816(acc[i][jp * 2 + h], ah[i], bh[2 * h], bh[2 * h + 1]);
                    }
                }
            }

            if (g == 0) {
                // ---- s2 epilogue: s2' = clip(0.5*(s2 + X + P2)); emit fp16 image to A2[nxt]
                char* a2n = sm + SM_A2 + (cur ^ 1) * 65536;
#pragma unroll
                for (int i = 0; i < 2; i++) {
                    int r = wm + i * 16 + (lane >> 2);
#pragma unroll
                    for (int j = 0; j < 8; j++) {
                        int c = wn + j * 8 + 2 * (lane & 3);
#pragma unroll
                        for (int half = 0; half < 2; half++) {
                            int m = r + half * 8;
                            size_t gr = row0 + m;
                            float p0 = acc[i][j][half * 2], p1 = acc[i][j][half * 2 + 1];
                            float2 xo = *(const float2*)(g_X + gr * H + c);
                            float2 so = *(const float2*)(s2in + gr * H + c);
                            float2 ov;
                            ov.x = rho_f(0.5f * (so.x + xo.x + p0));
                            ov.y = rho_f(0.5f * (so.y + xo.y + p1));
                            *(float2*)(s2out + gr * H + c) = ov;
                            *(uint32_t*)(a2n + img_off(m, c)) = pack_h2(ov.x, ov.y);
                        }
                    }
                }
                // ---- s0 update: warp-per-row; rho(s1) from A1 image (old), W0 in regs
                {
                    const float* W0s = (const float*)(sm + SM_W0);
                    const float* b0s = (const float*)(sm + SM_B0V);
                    float4 wreg[OUTD][2];
#pragma unroll
                    for (int o = 0; o < OUTD; o++) {
                        wreg[o][0] = *(const float4*)(W0s + o * H + lane * 8);
                        wreg[o][1] = *(const float4*)(W0s + o * H + lane * 8 + 4);
                    }
#pragma unroll 1
                    for (int rr = 0; rr < 8; rr++) {
                        int r = wid * 8 + rr;
                        uint32_t aoff = (uint32_t)r * 512u + (((uint32_t)(lane ^ (r & 7))) << 4);
                        uint4 hv = *(const uint4*)(sm + SM_A1 + aoff);
                        float2 f0 = __half22float2(*(__half2*)&hv.x);
                        float2 f1 = __half22float2(*(__half2*)&hv.y);
                        float2 f2 = __half22float2(*(__half2*)&hv.z);
                        float2 f3 = __half22float2(*(__half2*)&hv.w);
                        float accs[OUTD];
#pragma unroll
                        for (int o = 0; o < OUTD; o++) {
                            float4 w0 = wreg[o][0], w1 = wreg[o][1];
                            accs[o] = f0.x * w0.x + f0.y * w0.y + f1.x * w0.z + f1.y * w0.w
                                    + f2.x * w1.x + f2.y * w1.y + f3.x * w1.z + f3.y * w1.w;
                        }
#pragma unroll
                        for (int d = 16; d; d >>= 1)
#pragma unroll
                            for (int o = 0; o < OUTD; o++)
                                accs[o] += __shfl_xor_sync(0xffffffffu, accs[o], d);
                        if (lane == 0) {
#pragma unroll
                            for (int o = 0; o < OUTD; o++) {
                                float s = s0in[(row0 + r) * OUTD + o];
                                s0out[(row0 + r) * OUTD + o] = rho_f(0.5f * (s + accs[o] + b0s[o]));
                            }
                        }
                    }
                }
            } else {
                // ---- s1 epilogue: s1' = clip(0.5*(s1 + P1)); update A1 image in place
                // (all A1 readers this step — g0 GEMM + s0 update — finished before the
                //  g1 chunk-loop barriers)
#pragma unroll
                for (int i = 0; i < 2; i++) {
                    int r = wm + i * 16 + (lane >> 2);
#pragma unroll
                    for (int j = 0; j < 8; j++) {
                        int c = wn + j * 8 + 2 * (lane & 3);
#pragma unroll
                        for (int half = 0; half < 2; half++) {
                            int m = r + half * 8;
                            size_t gr = row0 + m;
                            float p0 = acc[i][j][half * 2], p1 = acc[i][j][half * 2 + 1];
                            float2 so = *(const float2*)(s1in + gr * H + c);
                            float2 ov;
                            ov.x = rho_f(0.5f * (so.x + p0));
                            ov.y = rho_f(0.5f * (so.y + p1));
                            *(float2*)(s1out + gr * H + c) = ov;
                            *(uint32_t*)(sm + SM_A1 + img_off(m, c)) = pack_h2(ov.x, ov.y);
                        }
                    }
                }
            }
        }

        cur ^= 1;
        __syncthreads();   // A1/A2 image writes + rs0 reuse ordered before next step
    }
    cpasync_wait0();       // drain the final (unused) prefetch
}

// ---------------- launch ----------------
extern "C" void kernel_launch(void* const* d_in, const int* in_sizes, int n_in,
                              void* d_out, int out_size)
{
    (void)in_sizes; (void)n_in; (void)out_size;
    const float* data = (const float*)d_in[0];
    const float* s0   = (const float*)d_in[1];
    const float* s1   = (const float*)d_in[2];
    const float* s2   = (const float*)d_in[3];
    const float* W0   = (const float*)d_in[4];
    const float* b0   = (const float*)d_in[5];
    const float* W2   = (const float*)d_in[6];
    const float* b2   = (const float*)d_in[7];
    const float* W4   = (const float*)d_in[8];
    const float* b4   = (const float*)d_in[9];
    float* out = (float*)d_out;

    cudaFuncSetAttribute(step_persist, cudaFuncAttributeMaxDynamicSharedMemorySize, SM_TOTAL);

    img_kernel<<<H, H2>>>(W2, W0, b2);
    x_kernel<<<dim3(BATCH / 64, H / 64), 256>>>(data, W4, b4);
    step_persist<<<BATCH / MROWS, NTHR, SM_TOTAL>>>(s0, s1, s2, out, W0, b0);
}

// round 16
// speedup vs baseline: 2.4675x; 1.5995x over previous
#include <cuda_runtime.h>
#include <cuda_fp16.h>
#include <cstdint>

#define BATCH 16384
#define H 256
#define H2 288
#define OUTD 10
#define IND 784
#define TSTEPS 50
#define MROWS 128
#define NTHR 512

typedef unsigned long long ull;

// -------- device scratch --------
__device__ float g_X[BATCH * H];
// fp16 weight images in [k][n] layout (n contiguous), XOR-swizzled 16B chunks.
// B1[k][n] = W2[k][n]  (P2 = rho(s1) @ W2)
// B2e: rows 0..255 = W2[n][k] (P1 = rho(s2) @ W2^T); rows 256+o = W0[o][n];
//      row 266 = b2[n]; rows 267..287 = 0   (chunk 16 folds b2 + rho(s0)@W0)
__device__ __half g_B1[H * H], g_B2e[H2 * H];

__device__ __forceinline__ float rho_f(float x) { return fminf(fmaxf(x, 0.0f), 1.0f); }

__device__ __forceinline__ ull pack2(float a, float b) {
    ull r; asm("mov.b64 %0, {%1, %2};" : "=l"(r) : "f"(a), "f"(b)); return r;
}
__device__ __forceinline__ void fma2(ull &d, ull a, ull b) {
    asm("fma.rn.f32x2 %0, %1, %2, %0;" : "+l"(d) : "l"(a), "l"(b));
}
__device__ __forceinline__ float2 unpack2(ull v) {
    float2 f; asm("mov.b64 {%0, %1}, %2;" : "=f"(f.x), "=f"(f.y) : "l"(v)); return f;
}
__device__ __forceinline__ void cpasync16(char* dst, const char* src) {
    unsigned d = (unsigned)__cvta_generic_to_shared(dst);
    asm volatile("cp.async.cg.shared.global [%0], [%1], 16;" :: "r"(d), "l"(src));
}
__device__ __forceinline__ void cpasync_commit() { asm volatile("cp.async.commit_group;"); }
__device__ __forceinline__ void cpasync_wait0()  { asm volatile("cp.async.wait_group 0;"); }

__device__ __forceinline__ uint32_t smem_u32(const void* p) {
    uint32_t a;
    asm("{ .reg .u64 t; cvta.to.shared.u64 t, %1; cvt.u32.u64 %0, t; }" : "=r"(a) : "l"(p));
    return a;
}
__device__ __forceinline__ void ldsm_x4(uint32_t* r, uint32_t addr) {
    asm volatile("ldmatrix.sync.aligned.m8n8.x4.shared.b16 {%0,%1,%2,%3}, [%4];"
                 : "=r"(r[0]), "=r"(r[1]), "=r"(r[2]), "=r"(r[3]) : "r"(addr));
}
__device__ __forceinline__ void ldsm_x4_t(uint32_t* r, uint32_t addr) {
    asm volatile("ldmatrix.sync.aligned.m8n8.x4.trans.shared.b16 {%0,%1,%2,%3}, [%4];"
                 : "=r"(r[0]), "=r"(r[1]), "=r"(r[2]), "=r"(r[3]) : "r"(addr));
}
__device__ __forceinline__ void mma16816(float* c, const uint32_t* a, uint32_t b0, uint32_t b1) {
    asm volatile("mma.sync.aligned.m16n8k16.row.col.f32.f16.f16.f32 "
        "{%0,%1,%2,%3}, {%4,%5,%6,%7}, {%8,%9}, {%0,%1,%2,%3};"
        : "+f"(c[0]), "+f"(c[1]), "+f"(c[2]), "+f"(c[3])
        : "r"(a[0]), "r"(a[1]), "r"(a[2]), "r"(a[3]), "r"(b0), "r"(b1));
}
__device__ __forceinline__ uint32_t pack_h2(float a, float b) {
    __half ha = __float2half(a), hb = __float2half(b);
    return ((uint32_t)__half_as_ushort(hb) << 16) | __half_as_ushort(ha);
}
// byte offset of element (m, k) in a 128x256 swizzled fp16 image
__device__ __forceinline__ uint32_t img_off(int m, int k) {
    return (uint32_t)m * 512u + ((((uint32_t)k >> 3) ^ ((uint32_t)m & 7u)) << 4)
         + ((uint32_t)k & 7u) * 2u;
}

// ---------------- build fp16 weight images ----------------
__global__ void __launch_bounds__(H2) img_kernel(
    const float* __restrict__ W2, const float* __restrict__ W0,
    const float* __restrict__ b2)
{
    int n = blockIdx.x, k = threadIdx.x;
    uint32_t off = (uint32_t)k * 512u + ((((uint32_t)n >> 3) ^ ((uint32_t)k & 7u)) << 4)
                 + ((uint32_t)n & 7u) * 2u;
    if (k < H)
        *(__half*)((char*)g_B1 + off) = __float2half(W2[k * H + n]);
    float w;
    if (k < H)              w = W2[n * H + k];
    else if (k < H + OUTD)  w = W0[(k - H) * H + n];
    else if (k == H + OUTD) w = b2[n];
    else                    w = 0.f;
    *(__half*)((char*)g_B2e + off) = __float2half(w);
}

// ---------------- prefix: X = rho(data) @ W4.T + b4 (fp32, once) ----------------
__global__ void __launch_bounds__(256) x_kernel(
    const float* __restrict__ data, const float* __restrict__ W4,
    const float* __restrict__ b4)
{
    __shared__ float As[16 * 66];
    __shared__ float Bs[16 * 66];
    const int tid = threadIdx.x;
    const int i0 = blockIdx.x * 64, j0 = blockIdx.y * 64;
    const int tx = tid & 15, ty = tid >> 4;
    const int kk = tid & 15, rr = tid >> 4;

    ull acc[4][2] = {};
    for (int k0 = 0; k0 < IND; k0 += 16) {
#pragma unroll
        for (int q = 0; q < 4; q++) {
            int r = rr + q * 16;
            As[kk * 66 + r] = rho_f(data[(size_t)(i0 + r) * IND + k0 + kk]);
            Bs[kk * 66 + r] = W4[(size_t)(j0 + r) * IND + k0 + kk];
        }
        __syncthreads();
#pragma unroll
        for (int k = 0; k < 16; k++) {
            ull a[4];
#pragma unroll
            for (int i = 0; i < 4; i++) {
                float av = As[k * 66 + ty * 4 + i];
                a[i] = pack2(av, av);
            }
            ull w0 = *(const ull*)(Bs + k * 66 + tx * 2);
            ull w1 = *(const ull*)(Bs + k * 66 + 32 + tx * 2);
#pragma unroll
            for (int i = 0; i < 4; i++) { fma2(acc[i][0], a[i], w0); fma2(acc[i][1], a[i], w1); }
        }
        __syncthreads();
    }
#pragma unroll
    for (int i = 0; i < 4; i++) {
        size_t row = (size_t)i0 + ty * 4 + i;
        float2 p0 = unpack2(acc[i][0]), p1 = unpack2(acc[i][1]);
        int j0a = j0 + tx * 2, j0b = j0 + 32 + tx * 2;
        *(float2*)(g_X + row * H + j0a) = make_float2(p0.x + b4[j0a], p0.y + b4[j0a + 1]);
        *(float2*)(g_X + row * H + j0b) = make_float2(p1.x + b4[j0b], p1.y + b4[j0b + 1]);
    }
}

// ---------------- SMEM layout (bytes) ----------------
#define SM_A1   0                      // [128][256] fp16 swizzled, persistent s1 state
#define SM_A2   65536                  // 2 x 64KB double-buffered s2 state
#define SM_B    196608                 // 2 bufs x 8KB (16 k-rows each)
#define SM_W0   212992                 // [10][256] fp16 = 5120
#define SM_RS0  218112                 // 2 x [128][10] f32 = 10240 (s0 state, fp32)
#define SM_B0V  228352
#define SM_TOTAL (SM_B0V + 64)

// initial stage: state [128][256] -> fp16 swizzled image (state in [0,1])
__device__ __forceinline__ void stage_A(const float* __restrict__ sin, size_t row0,
                                        char* smA, int tid)
{
#pragma unroll
    for (int it = 0; it < 8; it++) {
        int idx = it * NTHR + tid;
        int m = idx >> 5, ch = idx & 31, k = ch << 3;
        float4 v0 = *(const float4*)(sin + (row0 + m) * H + k);
        float4 v1 = *(const float4*)(sin + (row0 + m) * H + k + 4);
        uint32_t h[4];
        h[0] = pack_h2(v0.x, v0.y); h[1] = pack_h2(v0.z, v0.w);
        h[2] = pack_h2(v1.x, v1.y); h[3] = pack_h2(v1.z, v1.w);
        uint32_t off = (uint32_t)m * 512u + (((uint32_t)(ch ^ (m & 7))) << 4);
        *(uint4*)(smA + off) = make_uint4(h[0], h[1], h[2], h[3]);
    }
}

// prefetch one 16-k-row weight chunk (8KB) into buffer buf
__device__ __forceinline__ void prefetch_chunk(char* sm, int buf, int tid,
                                               const char* img, int chunk)
{
    cpasync16(sm + SM_B + buf * 8192 + tid * 16,
              img + (size_t)chunk * 8192 + tid * 16);
    cpasync_commit();
}

__global__ void __launch_bounds__(NTHR, 1) step_persist(
    const float* __restrict__ s0a, const float* __restrict__ s1a,
    const float* __restrict__ s2a, float* __restrict__ dout,
    const float* __restrict__ W0, const float* __restrict__ b0)
{
    extern __shared__ char sm[];
    const uint32_t smb = smem_u32(sm);
    const int tid = threadIdx.x;
    const int lane = tid & 31, wid = tid >> 5;
    const size_t row0 = (size_t)blockIdx.x * MROWS;

    const int wm = (wid & 3) * 32;
    const int wn = (wid >> 2) * 64;

    float* dout0 = dout;
    float* dout1 = dout + BATCH * OUTD;
    float* dout2 = dout + BATCH * OUTD + (size_t)BATCH * H;

    // one-time staging
    for (int i = tid; i < OUTD * H; i += NTHR)
        ((__half*)(sm + SM_W0))[i] = __float2half(W0[i]);
    if (tid < OUTD) ((float*)(sm + SM_B0V))[tid] = b0[tid];
    for (int i = tid; i < MROWS * OUTD; i += NTHR)
        ((float*)(sm + SM_RS0))[i] = s0a[row0 * OUTD + i];
    stage_A(s1a, row0, sm + SM_A1, tid);
    stage_A(s2a, row0, sm + SM_A2, tid);
    prefetch_chunk(sm, 0, tid, (const char*)g_B1, 0);
    __syncthreads();

    int cur = 0;   // active A2 buffer
    int pb = 0;    // rotating B buffer parity
    float acc[2][8][4];

#pragma unroll 1
    for (int t = 0; t < TSTEPS; t++) {
        const int last = (t == TSTEPS - 1);
        const float* rs0c = (const float*)(sm + SM_RS0 + (t & 1) * 5120);
        float* rs0n = (float*)(sm + SM_RS0 + ((t & 1) ^ 1) * 5120);

#pragma unroll 1
        for (int g = 0; g < 2; g++) {
            const char* img = g ? (const char*)g_B2e : (const char*)g_B1;
            const uint32_t abase = smb + (g ? (SM_A2 + cur * 65536) : SM_A1);
            const int nchunks = g ? 17 : 16;

#pragma unroll
            for (int i = 0; i < 2; i++)
#pragma unroll
                for (int j = 0; j < 8; j++)
#pragma unroll
                    for (int q = 0; q < 4; q++) acc[i][j][q] = 0.f;

#pragma unroll 1
            for (int kc = 0; kc < nchunks; kc++) {
                const int buf = pb;
                cpasync_wait0();
                __syncthreads();
                if (kc < nchunks - 1)
                    prefetch_chunk(sm, buf ^ 1, tid, img, kc + 1);
                else if (g == 0)
                    prefetch_chunk(sm, buf ^ 1, tid, (const char*)g_B2e, 0);
                else
                    prefetch_chunk(sm, buf ^ 1, tid, (const char*)g_B1, 0); // next step
                pb ^= 1;

                const uint32_t bbase = smb + SM_B + buf * 8192;

                if (g == 1 && kc == 16) {
                    // fold chunk: A = [rs0 | 1 | 0] composed in regs (global k 256..271)
                    const int tq = lane & 3, gq = lane >> 2;
                    uint32_t ae[2][4];
#pragma unroll
                    for (int i = 0; i < 2; i++) {
                        int r0 = wm + i * 16 + gq, r1 = r0 + 8;
                        float v00 = rs0c[r0 * OUTD + 2 * tq], v01 = rs0c[r0 * OUTD + 2 * tq + 1];
                        float v10 = rs0c[r1 * OUTD + 2 * tq], v11 = rs0c[r1 * OUTD + 2 * tq + 1];
                        float v02, v03, v12, v13;
                        if (tq == 0) {
                            v02 = rs0c[r0 * OUTD + 8]; v03 = rs0c[r0 * OUTD + 9];
                            v12 = rs0c[r1 * OUTD + 8]; v13 = rs0c[r1 * OUTD + 9];
                        } else if (tq == 1) {
                            v02 = 1.f; v03 = 0.f; v12 = 1.f; v13 = 0.f;
                        } else {
                            v02 = v03 = v12 = v13 = 0.f;
                        }
                        ae[i][0] = pack_h2(v00, v01); ae[i][1] = pack_h2(v10, v11);
                        ae[i][2] = pack_h2(v02, v03); ae[i][3] = pack_h2(v12, v13);
                    }
                    const int kl = lane & 15;
#pragma unroll
                    for (int jp = 0; jp < 4; jp++) {
                        int nch = ((wn + jp * 16) >> 3) + (lane >> 4);
                        uint32_t boff = (uint32_t)kl * 512u + ((uint32_t)(nch ^ (kl & 7)) << 4);
                        uint32_t bh[4];
                        ldsm_x4_t(bh, bbase + boff);
#pragma unroll
                        for (int h = 0; h < 2; h++)
#pragma unroll
                            for (int i = 0; i < 2; i++)
                                mma16816(acc[i][jp * 2 + h], ae[i], bh[2 * h], bh[2 * h + 1]);
                    }
                } else {
                    const int kk = kc * 16;
                    uint32_t ah[2][4];
#pragma unroll
                    for (int i = 0; i < 2; i++) {
                        int mr = wm + i * 16 + (lane & 15);
                        uint32_t aoff = (uint32_t)mr * 512u
                                      + ((uint32_t)(((kk >> 3) + (lane >> 4)) ^ (mr & 7)) << 4);
                        ldsm_x4(ah[i], abase + aoff);
                    }
                    const int kl = lane & 15;
#pragma unroll
                    for (int jp = 0; jp < 4; jp++) {
                        int nch = ((wn + jp * 16) >> 3) + (lane >> 4);
                        uint32_t boff = (uint32_t)kl * 512u
                                      + ((uint32_t)(nch ^ (kl & 7)) << 4);
                        uint32_t bh[4];
                        ldsm_x4_t(bh, bbase + boff);
#pragma unroll
                        for (int h = 0; h < 2; h++)
#pragma unroll
                            for (int i = 0; i < 2; i++)
                                mma16816(acc[i][jp * 2 + h], ah[i], bh[2 * h], bh[2 * h + 1]);
                    }
                }
            }

            if (g == 0) {
                // ---- s2 epilogue: s2' = clip(0.5*(s2 + X + P2)); state is the A2 image
                char* a2c = sm + SM_A2 + cur * 65536;
                char* a2n = sm + SM_A2 + (cur ^ 1) * 65536;
#pragma unroll
                for (int i = 0; i < 2; i++) {
                    int r = wm + i * 16 + (lane >> 2);
#pragma unroll
                    for (int j = 0; j < 8; j++) {
                        int c = wn + j * 8 + 2 * (lane & 3);
#pragma unroll
                        for (int half = 0; half < 2; half++) {
                            int m = r + half * 8;
                            size_t gr = row0 + m;
                            uint32_t io = img_off(m, c);
                            float p0 = acc[i][j][half * 2], p1 = acc[i][j][half * 2 + 1];
                            float2 xo = *(const float2*)(g_X + gr * H + c);
                            float2 so = __half22float2(*(const __half2*)(a2c + io));
                            float2 ov;
                            ov.x = rho_f(0.5f * (so.x + xo.x + p0));
                            ov.y = rho_f(0.5f * (so.y + xo.y + p1));
                            *(uint32_t*)(a2n + io) = pack_h2(ov.x, ov.y);
                            if (last) *(float2*)(dout2 + gr * H + c) = ov;
                        }
                    }
                }
                // ---- s0 update: warp-per-row; rho(s1) from A1 image (old), W0 fp16 smem
                {
                    const __half* W0s = (const __half*)(sm + SM_W0);
                    const float* b0s = (const float*)(sm + SM_B0V);
                    float wr[OUTD][8];
#pragma unroll
                    for (int o = 0; o < OUTD; o++) {
                        uint4 wv = *(const uint4*)(W0s + o * H + lane * 8);
                        float2 a0 = __half22float2(*(__half2*)&wv.x);
                        float2 a1 = __half22float2(*(__half2*)&wv.y);
                        float2 a2 = __half22float2(*(__half2*)&wv.z);
                        float2 a3 = __half22float2(*(__half2*)&wv.w);
                        wr[o][0] = a0.x; wr[o][1] = a0.y; wr[o][2] = a1.x; wr[o][3] = a1.y;
                        wr[o][4] = a2.x; wr[o][5] = a2.y; wr[o][6] = a3.x; wr[o][7] = a3.y;
                    }
#pragma unroll 1
                    for (int rr = 0; rr < 8; rr++) {
                        int r = wid * 8 + rr;
                        uint32_t aoff = (uint32_t)r * 512u + (((uint32_t)(lane ^ (r & 7))) << 4);
                        uint4 hv = *(const uint4*)(sm + SM_A1 + aoff);
                        float2 f0 = __half22float2(*(__half2*)&hv.x);
                        float2 f1 = __half22float2(*(__half2*)&hv.y);
                        float2 f2 = __half22float2(*(__half2*)&hv.z);
                        float2 f3 = __half22float2(*(__half2*)&hv.w);
                        float accs[OUTD];
#pragma unroll
                        for (int o = 0; o < OUTD; o++) {
                            accs[o] = f0.x * wr[o][0] + f0.y * wr[o][1]
                                    + f1.x * wr[o][2] + f1.y * wr[o][3]
                                    + f2.x * wr[o][4] + f2.y * wr[o][5]
                                    + f3.x * wr[o][6] + f3.y * wr[o][7];
                        }
#pragma unroll
                        for (int d = 16; d; d >>= 1)
#pragma unroll
                            for (int o = 0; o < OUTD; o++)
                                accs[o] += __shfl_xor_sync(0xffffffffu, accs[o], d);
                        if (lane == 0) {
#pragma unroll
                            for (int o = 0; o < OUTD; o++) {
                                float s = rs0c[r * OUTD + o];
                                float nv = rho_f(0.5f * (s + accs[o] + b0s[o]));
                                rs0n[r * OUTD + o] = nv;
                                if (last) dout0[(row0 + r) * OUTD + o] = nv;
                            }
                        }
                    }
                }
            } else {
                // ---- s1 epilogue: s1' = clip(0.5*(s1 + P1)); update A1 image in place
                // (each thread reads exactly the positions it overwrites; all other A1
                //  readers this step finished before the g1 chunk-loop barriers)
#pragma unroll
                for (int i = 0; i < 2; i++) {
                    int r = wm + i * 16 + (lane >> 2);
#pragma unroll
                    for (int j = 0; j < 8; j++) {
                        int c = wn + j * 8 + 2 * (lane & 3);
#pragma unroll
                        for (int half = 0; half < 2; half++) {
                            int m = r + half * 8;
                            size_t gr = row0 + m;
                            uint32_t io = img_off(m, c);
                            float p0 = acc[i][j][half * 2], p1 = acc[i][j][half * 2 + 1];
                            float2 so = __half22float2(*(const __half2*)(sm + SM_A1 + io));
                            float2 ov;
                            ov.x = rho_f(0.5f * (so.x + p0));
                            ov.y = rho_f(0.5f * (so.y + p1));
                            *(uint32_t*)(sm + SM_A1 + io) = pack_h2(ov.x, ov.y);
                            if (last) *(float2*)(dout1 + gr * H + c) = ov;
                        }
                    }
                }
            }
        }

        cur ^= 1;
        __syncthreads();   // image + rs0 writes ordered before next step's readers
    }
    cpasync_wait0();       // drain the final (unused) prefetch
}

// ---------------- launch ----------------
extern "C" void kernel_launch(void* const* d_in, const int* in_sizes, int n_in,
                              void* d_out, int out_size)
{
    (void)in_sizes; (void)n_in; (void)out_size;
    const float* data = (const float*)d_in[0];
    const float* s0   = (const float*)d_in[1];
    const float* s1   = (const float*)d_in[2];
    const float* s2   = (const float*)d_in[3];
    const float* W0   = (const float*)d_in[4];
    const float* b0   = (const float*)d_in[5];
    const float* W2   = (const float*)d_in[6];
    const float* b2   = (const float*)d_in[7];
    const float* W4   = (const float*)d_in[8];
    const float* b4   = (const float*)d_in[9];
    float* out = (float*)d_out;

    cudaFuncSetAttribute(step_persist, cudaFuncAttributeMaxDynamicSharedMemorySize, SM_TOTAL);

    img_kernel<<<H, H2>>>(W2, W0, b2);
    x_kernel<<<dim3(BATCH / 64, H / 64), 256>>>(data, W4, b4);
    step_persist<<<BATCH / MROWS, NTHR, SM_TOTAL>>>(s0, s1, s2, out, W0, b0);
}